// round 7
// baseline (speedup 1.0000x reference)
#include <cuda_runtime.h>
#include <math.h>
#include <stdint.h>

// Problem constants
#define B_   32
#define T_   1024
#define IN_  64
#define H_   512
#define F_   63
#define G4_  2048           // 4*H
#define BT_  32768          // B*T
#define NCTA_LSTM 128

// ---------------- scratch (device globals; no runtime allocation) ----------------
__device__ float g_xw[BT_ * G4_];                 // x @ w_ih^T + b_ih + b_hh   [BT,4H]
__device__ float g_rout[BT_ * H_];                // LSTM outputs               [BT,H]
__device__ float g_shared[BT_ * H_];              // shared layer               [BT,H]
__device__ float g_ctx0[BT_ * H_];                // tmp_sa, then state ctx     [BT,H]
__device__ float g_ctx1[BT_ * H_];                // tmp_ra, then reward ctx    [BT,H]
__device__ float g_e[2 * BT_];                    // attention scores (sa, ra)
__device__ float g_hT[2][H_ * B_];                // double-buffered h, TRANSPOSED [j][b]
__device__ float g_cbuf[B_ * H_];                 // final c state
__device__ unsigned g_cnt   = 0;                  // grid barrier arrive counter
__device__ unsigned g_gen_v = 0;                  // grid barrier generation
__device__ unsigned g_abort = 0;                  // barrier watchdog latch (never set in healthy runs)

// ---------------- small helpers ----------------
__device__ __forceinline__ uint64_t ffma2(uint64_t a, uint64_t b, uint64_t c) {
    uint64_t d;
    asm("fma.rn.f32x2 %0, %1, %2, %3;" : "=l"(d) : "l"(a), "l"(b), "l"(c));
    return d;
}
__device__ __forceinline__ uint64_t pack2(float x) {
    uint64_t r;
    asm("mov.b64 %0, {%1, %1};" : "=l"(r) : "f"(x));
    return r;
}
__device__ __forceinline__ void unpack2(float& lo, float& hi, uint64_t v) {
    asm("mov.b64 {%0, %1}, %2;" : "=f"(lo), "=f"(hi) : "l"(v));
}
__device__ __forceinline__ float fast_tanh(float x) {
    return 1.f - 2.f / (1.f + __expf(2.f * x));
}
__device__ __forceinline__ float fast_sigmoid(float x) {
    return __fdividef(1.f, 1.f + __expf(-x));
}

// ---------------- init: h0 -> transposed h buffer (also clears watchdog state) ----------------
__global__ void init_state_kernel(const float* __restrict__ h0) {
    int i = blockIdx.x * blockDim.x + threadIdx.x;   // i = j*32 + b
    if (i == 0) { g_abort = 0; g_cnt = 0; }          // deterministic across graph replays
    if (i < B_ * H_) {
        int j = i >> 5, b = i & 31;
        g_hT[0][i] = h0[b * H_ + j];
    }
}

// ---------------- generic fp32 GEMM via packed f32x2 ----------------
// C[m,n] = sum_k A[m,k]*W[n,k] + bias(+bias2). BM=BN=64, BK=16, 256 threads.
// A values are pre-duplicated (a,a) in smem so the inner loop is pure FFMA2:
// per k: 3x LDS.128 + 8x FFMA2 (16 scalar FMA worth) -> FMA-pipe cycles halved.
__global__ void __launch_bounds__(256) gemm_bias_kernel(
    const float* __restrict__ A, const float* __restrict__ W,
    const float* __restrict__ bias, const float* __restrict__ bias2,
    float* __restrict__ C, int M, int N, int K)
{
    __shared__ uint64_t As2[16][68];   // (a,a) pairs [k][m], padded (row = 544B, 16B-aligned)
    __shared__ float    Ws[16][68];    // [k][n], padded (row = 272B, 16B-aligned)
    const int tid  = threadIdx.x;
    const int m0   = blockIdx.y * 64;
    const int n0   = blockIdx.x * 64;
    const int lrow = tid >> 2;
    const int lk   = (tid & 3) << 2;
    const int ty   = tid >> 4;
    const int tx   = tid & 15;

    uint64_t acc[4][2] = {};

    for (int k0 = 0; k0 < K; k0 += 16) {
        float4 av = *reinterpret_cast<const float4*>(&A[(size_t)(m0 + lrow) * K + k0 + lk]);
        float4 wv = make_float4(0.f, 0.f, 0.f, 0.f);
        if (n0 + lrow < N)
            wv = *reinterpret_cast<const float4*>(&W[(size_t)(n0 + lrow) * K + k0 + lk]);
        __syncthreads();
        As2[lk + 0][lrow] = pack2(av.x); As2[lk + 1][lrow] = pack2(av.y);
        As2[lk + 2][lrow] = pack2(av.z); As2[lk + 3][lrow] = pack2(av.w);
        Ws[lk + 0][lrow] = wv.x; Ws[lk + 1][lrow] = wv.y;
        Ws[lk + 2][lrow] = wv.z; Ws[lk + 3][lrow] = wv.w;
        __syncthreads();
        #pragma unroll
        for (int k = 0; k < 16; k++) {
            ulonglong2 a01 = *reinterpret_cast<const ulonglong2*>(&As2[k][ty * 4]);
            ulonglong2 a23 = *reinterpret_cast<const ulonglong2*>(&As2[k][ty * 4 + 2]);
            ulonglong2 w01 = *reinterpret_cast<const ulonglong2*>(&Ws[k][tx * 4]);
            acc[0][0] = ffma2(a01.x, w01.x, acc[0][0]);
            acc[0][1] = ffma2(a01.x, w01.y, acc[0][1]);
            acc[1][0] = ffma2(a01.y, w01.x, acc[1][0]);
            acc[1][1] = ffma2(a01.y, w01.y, acc[1][1]);
            acc[2][0] = ffma2(a23.x, w01.x, acc[2][0]);
            acc[2][1] = ffma2(a23.x, w01.y, acc[2][1]);
            acc[3][0] = ffma2(a23.y, w01.x, acc[3][0]);
            acc[3][1] = ffma2(a23.y, w01.y, acc[3][1]);
        }
    }

    #pragma unroll
    for (int i = 0; i < 4; i++) {
        int row = m0 + ty * 4 + i;
        #pragma unroll
        for (int jp = 0; jp < 2; jp++) {
            float lo, hi;
            unpack2(lo, hi, acc[i][jp]);
            int col = n0 + tx * 4 + jp * 2;
            if (col < N) {
                float v = lo;
                if (bias)  v += bias[col];
                if (bias2) v += bias2[col];
                C[(size_t)row * N + col] = v;
            }
            if (col + 1 < N) {
                float v = hi;
                if (bias)  v += bias[col + 1];
                if (bias2) v += bias2[col + 1];
                C[(size_t)row * N + col + 1] = v;
            }
        }
    }
}

// ---------------- attention score: e[row] = bv + sum_i v[i]*tanh(tmp[row,i]) ----------------
__global__ void __launch_bounds__(128) attn_e_kernel(
    const float* __restrict__ tmp, const float* __restrict__ v,
    const float* __restrict__ bv, float* __restrict__ e)
{
    const int row = blockIdx.x;
    const int tid = threadIdx.x;
    float p = 0.f;
    #pragma unroll
    for (int i = tid; i < H_; i += 128)
        p += v[i] * fast_tanh(tmp[(size_t)row * H_ + i]);
    #pragma unroll
    for (int off = 16; off > 0; off >>= 1)
        p += __shfl_down_sync(0xffffffffu, p, off);
    __shared__ float red[4];
    if ((tid & 31) == 0) red[tid >> 5] = p;
    __syncthreads();
    if (tid == 0) e[row] = red[0] + red[1] + red[2] + red[3] + bv[0];
}

// ---------------- persistent LSTM ----------------
// Grid barrier: arrive via ONE atomicAdd per CTA; WAIT via plain volatile loads
// (no atomic-ALU serialization at L2 -- the R5 atomic-poll storm was ~9K cyc/step).
// Bounded spin + global abort latch keeps it hang-proof: on any pathology all
// CTAs degrade to no-op barriers and the kernel exits with wrong output
// (bench signal) instead of a dead container.
__device__ __forceinline__ void grid_sync_128() {
    __syncthreads();
    if (threadIdx.x == 0) {
        volatile unsigned* vabort = &g_abort;
        volatile unsigned* vgen   = &g_gen_v;
        if (*vabort == 0u) {
            __threadfence();
            unsigned gen = *vgen;                        // read own generation BEFORE arriving
            if (atomicAdd(&g_cnt, 1u) == NCTA_LSTM - 1) {
                *(volatile unsigned*)&g_cnt = 0;
                __threadfence();
                *vgen = gen + 1;                         // release
            } else {
                unsigned spin = 0;
                while (*vgen == gen) {
                    if (((++spin) & 4095u) == 0u) {
                        if (*vabort != 0u) break;
                        if (spin > (1u << 22)) { atomicExch(&g_abort, 1u); break; }
                    }
                }
            }
            __threadfence();
        }
    }
    __syncthreads();
}

// CTA c owns h-columns J = {4c..4c+3}: gate rows g*512 + J for g in {i,f,g,o}.
// Thread (ri = tid&15, kg = tid>>4): row ri = g*4+jloc of the 16 rows, K-slice kg (32 k).
// W slice lives in registers as packed (w,w) f32x2 for all 1024 steps.
// Phase A: 16x512x32 partial products via FFMA2 over batch pairs -> intra-CTA smem partials.
// Gate stage (tid<128): reduce 16 K-groups + xw, activations, h/c update. ONE grid sync/step.
__global__ void __launch_bounds__(256, 1) lstm_kernel(
    const float* __restrict__ xw, const float* __restrict__ w_hh,
    const float* __restrict__ c0)
{
    extern __shared__ char smem_raw[];
    float*    hs   = reinterpret_cast<float*>(smem_raw);            // [512][32] = 64KB
    uint64_t* part = reinterpret_cast<uint64_t*>(smem_raw + 65536); // 16 kg * (16 ri * 18) u64 = 36KB

    const int cta  = blockIdx.x;
    const int tid  = threadIdx.x;
    const int ri   = tid & 15;
    const int kg   = tid >> 4;
    const int warp = tid >> 5;
    const int lane = tid & 31;
    const int c4   = cta * 4;

    // W_hh slice resident in registers (packed pairs) for all steps
    uint64_t wpack[32];
    {
        const int g = ri >> 2, jl = ri & 3;
        const float* wrow = w_hh + (size_t)(g * H_ + c4 + jl) * H_ + (kg << 5);
        #pragma unroll
        for (int q = 0; q < 8; q++) {
            float4 wv = *reinterpret_cast<const float4*>(wrow + q * 4);
            wpack[q * 4 + 0] = pack2(wv.x);
            wpack[q * 4 + 1] = pack2(wv.y);
            wpack[q * 4 + 2] = pack2(wv.z);
            wpack[q * 4 + 3] = pack2(wv.w);
        }
    }

    // gate-stage ownership (threads 0..127): cell (jloc, bb), c in register
    const int jloc = tid >> 5;
    const int bb   = tid & 31;
    float cstate = 0.f;
    if (tid < 128) cstate = c0[bb * H_ + c4 + jloc];

    for (int t = 0; t < T_; t++) {
        const int cur = t & 1;

        // Warp-local h slice load: warp w needs K-slices {2w, 2w+1} = 2048 contiguous
        // floats of transposed h. Bypass L1 (written by other CTAs last step).
        {
            const float4* src = reinterpret_cast<const float4*>(&g_hT[cur][warp * 2048]);
            float4*       dst = reinterpret_cast<float4*>(&hs[warp * 2048]);
            #pragma unroll
            for (int i = 0; i < 16; i++)
                dst[i * 32 + lane] = __ldcg(&src[i * 32 + lane]);
        }

        // Prefetch xw gate biases for (bb, t) — latency hidden under FMA phase
        float xr0 = 0.f, xr1 = 0.f, xr2 = 0.f, xr3 = 0.f;
        if (tid < 128) {
            const float* xp = xw + (size_t)((bb << 10) | t) * G4_ + c4 + jloc;
            xr0 = __ldcg(xp);
            xr1 = __ldcg(xp + H_);
            xr2 = __ldcg(xp + 2 * H_);
            xr3 = __ldcg(xp + 3 * H_);
        }
        __syncwarp();

        // Phase A: 32 k x 32 b per thread via packed FFMA2 (b-pairs)
        uint64_t acc[16];
        #pragma unroll
        for (int q = 0; q < 16; q++) acc[q] = 0ull;
        const float* hsl = hs + (kg << 10);
        #pragma unroll
        for (int k = 0; k < 32; k++) {
            const ulonglong2* hp = reinterpret_cast<const ulonglong2*>(hsl + (k << 5));
            const uint64_t w2 = wpack[k];
            #pragma unroll
            for (int q = 0; q < 8; q++) {
                ulonglong2 hv = hp[q];
                acc[2 * q]     = ffma2(w2, hv.x, acc[2 * q]);
                acc[2 * q + 1] = ffma2(w2, hv.y, acc[2 * q + 1]);
            }
        }
        // store partials (ri-stride padded to 18 u64 = 144B)
        {
            ulonglong2* pp = reinterpret_cast<ulonglong2*>(part + kg * 288 + ri * 18);
            #pragma unroll
            for (int q = 0; q < 8; q++)
                pp[q] = make_ulonglong2(acc[2 * q], acc[2 * q + 1]);
        }
        __syncthreads();

        // Gate stage: reduce K-groups + activations + state update
        if (tid < 128) {
            const float* pf = reinterpret_cast<const float*>(part);
            float s0 = xr0, s1 = xr1, s2 = xr2, s3 = xr3;
            #pragma unroll
            for (int q = 0; q < 16; q++) {
                const float* base = pf + q * 576 + bb;
                s0 += base[(0 * 4 + jloc) * 36];
                s1 += base[(1 * 4 + jloc) * 36];
                s2 += base[(2 * 4 + jloc) * 36];
                s3 += base[(3 * 4 + jloc) * 36];
            }
            float ig = fast_sigmoid(s0);
            float fg = fast_sigmoid(s1);
            float gg = fast_tanh(s2);
            float og = fast_sigmoid(s3);
            cstate   = fg * cstate + ig * gg;
            float hn = og * fast_tanh(cstate);
            g_hT[cur ^ 1][(c4 + jloc) * 32 + bb] = hn;                  // coalesced (b-lanes)
            g_rout[(size_t)((bb << 10) | t) * H_ + c4 + jloc] = hn;     // standard layout
        }
        grid_sync_128();
    }
    if (tid < 128) g_cbuf[bb * H_ + c4 + jloc] = cstate;
}

// ---------------- causal softmax pooling via online cumulative scan ----------------
__global__ void __launch_bounds__(512) attn_scan_kernel() {
    const int a = blockIdx.x >> 5;     // 0 = state attn, 1 = reward attn
    const int b = blockIdx.x & 31;
    const float* e   = &g_e[a * BT_ + b * T_];
    const float* sh  = &g_shared[(size_t)b * T_ * H_];
    float*       ctx = (a == 0) ? &g_ctx0[(size_t)b * T_ * H_]
                                : &g_ctx1[(size_t)b * T_ * H_];
    const int i = threadIdx.x;
    float m = -1e30f, Z = 0.f, s = 0.f;
    for (int t = 0; t < T_; t++) {
        float ev = e[t];
        float x  = sh[(size_t)t * H_ + i];
        float mn = fmaxf(m, ev);
        float corr = __expf(m - mn);
        float w    = __expf(ev - mn);
        Z = Z * corr + w;
        s = s * corr + w * x;
        m = mn;
        ctx[(size_t)t * H_ + i] = __fdividef(s, Z);
    }
}

// ---------------- reward head: dot(ctx_ra, w_rw) + b_rw ----------------
__global__ void __launch_bounds__(256) reward_kernel(
    const float* __restrict__ w_rw, const float* __restrict__ b_rw,
    float* __restrict__ out)
{
    const int warp = threadIdx.x >> 5, lane = threadIdx.x & 31;
    const int token = blockIdx.x * 8 + warp;
    const float* c = &g_ctx1[(size_t)token * H_];
    float p = 0.f;
    #pragma unroll
    for (int i = lane; i < H_; i += 32) p += c[i] * w_rw[i];
    #pragma unroll
    for (int off = 16; off > 0; off >>= 1)
        p += __shfl_down_sync(0xffffffffu, p, off);
    if (lane == 0) out[token] = p + b_rw[0];
}

// ---------------- pack hT, cT ----------------
__global__ void pack_kernel(float* __restrict__ out_h, float* __restrict__ out_c) {
    int i = blockIdx.x * blockDim.x + threadIdx.x;   // i = b*512 + j
    if (i < B_ * H_) {
        int b = i >> 9, j = i & 511;
        out_h[i] = g_hT[0][j * 32 + b];   // T even: final h lives in buffer 0
        out_c[i] = g_cbuf[i];
    }
}

// ---------------- launch ----------------
extern "C" void kernel_launch(void* const* d_in, const int* in_sizes, int n_in,
                              void* d_out, int out_size) {
    const float* x     = (const float*)d_in[0];
    // d_in[1] = x_lengths (int64), all == T -> pack/pad identity, ignored
    const float* h0    = (const float*)d_in[2];
    const float* c0    = (const float*)d_in[3];
    const float* w_ih  = (const float*)d_in[4];
    const float* w_hh  = (const float*)d_in[5];
    const float* b_ih  = (const float*)d_in[6];
    const float* b_hh  = (const float*)d_in[7];
    const float* w_sh  = (const float*)d_in[8];
    const float* b_sh  = (const float*)d_in[9];
    const float* w_sa  = (const float*)d_in[10];
    const float* b_sa  = (const float*)d_in[11];
    const float* v_sa  = (const float*)d_in[12];
    const float* bv_sa = (const float*)d_in[13];
    const float* w_ra  = (const float*)d_in[14];
    const float* b_ra  = (const float*)d_in[15];
    const float* v_ra  = (const float*)d_in[16];
    const float* bv_ra = (const float*)d_in[17];
    const float* w_st  = (const float*)d_in[18];
    const float* b_st  = (const float*)d_in[19];
    const float* w_rw  = (const float*)d_in[20];
    const float* b_rw  = (const float*)d_in[21];

    float* out        = (float*)d_out;
    float* out_state  = out;                       // [B,T,F]  = 2064384
    float* out_reward = out + 2064384;             // [B,T,1]  = 32768
    float* out_hT     = out + 2097152;             // [B,H]    = 16384
    float* out_cT     = out + 2113536;             // [B,H]    = 16384

    float *p_xw, *p_rout, *p_shared, *p_ctx0, *p_ctx1, *p_e;
    cudaGetSymbolAddress((void**)&p_xw,     g_xw);
    cudaGetSymbolAddress((void**)&p_rout,   g_rout);
    cudaGetSymbolAddress((void**)&p_shared, g_shared);
    cudaGetSymbolAddress((void**)&p_ctx0,   g_ctx0);
    cudaGetSymbolAddress((void**)&p_ctx1,   g_ctx1);
    cudaGetSymbolAddress((void**)&p_e,      g_e);

    const int LSTM_SMEM = 65536 + 36864;   // hs (64KB) + partials (36KB)
    cudaFuncSetAttribute(lstm_kernel, cudaFuncAttributeMaxDynamicSharedMemorySize, LSTM_SMEM);

    // 1) state init (transposed h buffer) + watchdog reset
    init_state_kernel<<<64, 256>>>(h0);
    // 2) input projection: xw = x @ w_ih^T + b_ih + b_hh    [BT,2048], K=64
    gemm_bias_kernel<<<dim3(G4_ / 64, BT_ / 64), 256>>>(x, w_ih, b_ih, b_hh, p_xw, BT_, G4_, IN_);
    // 3) persistent LSTM over T=1024 steps
    lstm_kernel<<<NCTA_LSTM, 256, LSTM_SMEM>>>(p_xw, w_hh, c0);
    // 4) shared layer: [BT,512] = rout @ w_sh^T + b_sh
    gemm_bias_kernel<<<dim3(H_ / 64, BT_ / 64), 256>>>(p_rout, w_sh, b_sh, nullptr, p_shared, BT_, H_, H_);
    // 5) state-attention scores
    gemm_bias_kernel<<<dim3(H_ / 64, BT_ / 64), 256>>>(p_shared, w_sa, b_sa, nullptr, p_ctx0, BT_, H_, H_);
    attn_e_kernel<<<BT_, 128>>>(p_ctx0, v_sa, bv_sa, p_e);
    // 6) reward-attention scores
    gemm_bias_kernel<<<dim3(H_ / 64, BT_ / 64), 256>>>(p_shared, w_ra, b_ra, nullptr, p_ctx1, BT_, H_, H_);
    attn_e_kernel<<<BT_, 128>>>(p_ctx1, v_ra, bv_ra, p_e + BT_);
    // 7) causal softmax pooling (both attentions), overwrites ctx buffers
    attn_scan_kernel<<<64, 512>>>();
    // 8) state head -> d_out directly
    gemm_bias_kernel<<<dim3(1, BT_ / 64), 256>>>(p_ctx0, w_st, b_st, nullptr, out_state, BT_, F_, H_);
    // 9) reward head
    reward_kernel<<<4096, 256>>>(w_rw, b_rw, out_reward);
    // 10) final states
    pack_kernel<<<64, 256>>>(out_hT, out_cT);
}

// round 9
// speedup vs baseline: 1.5667x; 1.5667x over previous
#include <cuda_runtime.h>
#include <math.h>
#include <stdint.h>

// Problem constants
#define B_   32
#define T_   1024
#define IN_  64
#define H_   512
#define F_   63
#define G4_  2048           // 4*H
#define BT_  32768          // B*T
#define NCTA_LSTM 128

// ---------------- scratch (device globals; no runtime allocation) ----------------
__device__ float g_xw[BT_ * G4_];                 // x @ w_ih^T + b_ih + b_hh   [BT,4H]
__device__ float g_rout[BT_ * H_];                // LSTM outputs               [BT,H]
__device__ float g_shared[BT_ * H_];              // shared layer               [BT,H]
__device__ float g_ctx0[BT_ * H_];                // tmp_sa, then state ctx     [BT,H]
__device__ float g_ctx1[BT_ * H_];                // tmp_ra, then reward ctx    [BT,H]
__device__ float g_e[2 * BT_];                    // attention scores (sa, ra)
__device__ float g_hT[2][H_ * B_];                // double-buffered h, TRANSPOSED [j][b]
__device__ float g_cbuf[B_ * H_];                 // final c state
__device__ unsigned g_cnt   = 0;                  // grid barrier arrive counter
__device__ unsigned g_gen_v = 0;                  // grid barrier generation
__device__ unsigned g_abort = 0;                  // barrier watchdog latch (never set in healthy runs)

// ---------------- small helpers ----------------
__device__ __forceinline__ uint64_t ffma2(uint64_t a, uint64_t b, uint64_t c) {
    uint64_t d;
    asm("fma.rn.f32x2 %0, %1, %2, %3;" : "=l"(d) : "l"(a), "l"(b), "l"(c));
    return d;
}
__device__ __forceinline__ uint64_t pack2(float x) {
    uint64_t r;
    asm("mov.b64 %0, {%1, %1};" : "=l"(r) : "f"(x));
    return r;
}
__device__ __forceinline__ float fast_tanh(float x) {
    return 1.f - 2.f / (1.f + __expf(2.f * x));
}
__device__ __forceinline__ float fast_sigmoid(float x) {
    return __fdividef(1.f, 1.f + __expf(-x));
}

// ---------------- init: h0 -> transposed h buffer (also clears watchdog state) ----------------
__global__ void init_state_kernel(const float* __restrict__ h0) {
    int i = blockIdx.x * blockDim.x + threadIdx.x;   // i = j*32 + b
    if (i == 0) { g_abort = 0; g_cnt = 0; }          // deterministic across graph replays
    if (i < B_ * H_) {
        int j = i >> 5, b = i & 31;
        g_hT[0][i] = h0[b * H_ + j];
    }
}

// ---------------- no-op spacer: positions lstm_kernel at launch index 5 so the
// harness's ncu capture (-s 5 -c 1) profiles the LSTM instead of a GEMM.
__global__ void spacer_kernel() {}

// ---------------- generic fp32 GEMM: C[m,n] = sum_k A[m,k]*W[n,k] + bias(+bias2) ----------------
// (R6 scalar version -- at the scalar-FMA roofline, 471us for H x H; known good.)
__global__ void __launch_bounds__(256) gemm_bias_kernel(
    const float* __restrict__ A, const float* __restrict__ W,
    const float* __restrict__ bias, const float* __restrict__ bias2,
    float* __restrict__ C, int M, int N, int K)
{
    __shared__ float As[16][68];
    __shared__ float Ws[16][68];
    const int tid  = threadIdx.x;
    const int m0   = blockIdx.y * 64;
    const int n0   = blockIdx.x * 64;
    const int lrow = tid >> 2;
    const int lk   = (tid & 3) << 2;
    const int ty   = tid >> 4;
    const int tx   = tid & 15;

    float acc[4][4] = {};

    for (int k0 = 0; k0 < K; k0 += 16) {
        float4 av = *reinterpret_cast<const float4*>(&A[(size_t)(m0 + lrow) * K + k0 + lk]);
        float4 wv = make_float4(0.f, 0.f, 0.f, 0.f);
        if (n0 + lrow < N)
            wv = *reinterpret_cast<const float4*>(&W[(size_t)(n0 + lrow) * K + k0 + lk]);
        __syncthreads();
        As[lk + 0][lrow] = av.x; As[lk + 1][lrow] = av.y;
        As[lk + 2][lrow] = av.z; As[lk + 3][lrow] = av.w;
        Ws[lk + 0][lrow] = wv.x; Ws[lk + 1][lrow] = wv.y;
        Ws[lk + 2][lrow] = wv.z; Ws[lk + 3][lrow] = wv.w;
        __syncthreads();
        #pragma unroll
        for (int k = 0; k < 16; k++) {
            float4 a4 = *reinterpret_cast<const float4*>(&As[k][ty * 4]);
            float4 w4 = *reinterpret_cast<const float4*>(&Ws[k][tx * 4]);
            float ar[4] = {a4.x, a4.y, a4.z, a4.w};
            float wr[4] = {w4.x, w4.y, w4.z, w4.w};
            #pragma unroll
            for (int i = 0; i < 4; i++)
                #pragma unroll
                for (int j = 0; j < 4; j++)
                    acc[i][j] = fmaf(ar[i], wr[j], acc[i][j]);
        }
    }

    #pragma unroll
    for (int i = 0; i < 4; i++) {
        int row = m0 + ty * 4 + i;
        #pragma unroll
        for (int j = 0; j < 4; j++) {
            int col = n0 + tx * 4 + j;
            if (col < N) {
                float v = acc[i][j];
                if (bias)  v += bias[col];
                if (bias2) v += bias2[col];
                C[(size_t)row * N + col] = v;
            }
        }
    }
}

// ---------------- attention score: e[row] = bv + sum_i v[i]*tanh(tmp[row,i]) ----------------
__global__ void __launch_bounds__(128) attn_e_kernel(
    const float* __restrict__ tmp, const float* __restrict__ v,
    const float* __restrict__ bv, float* __restrict__ e)
{
    const int row = blockIdx.x;
    const int tid = threadIdx.x;
    float p = 0.f;
    #pragma unroll
    for (int i = tid; i < H_; i += 128)
        p += v[i] * fast_tanh(tmp[(size_t)row * H_ + i]);
    #pragma unroll
    for (int off = 16; off > 0; off >>= 1)
        p += __shfl_down_sync(0xffffffffu, p, off);
    __shared__ float red[4];
    if ((tid & 31) == 0) red[tid >> 5] = p;
    __syncthreads();
    if (tid == 0) e[row] = red[0] + red[1] + red[2] + red[3] + bv[0];
}

// ---------------- persistent LSTM ----------------
// Grid barrier, R8 variant: arrive = ONE atomicAdd per CTA; release = atomicExch;
// WAIT = __ldcg plain L2 loads + nanosleep (no RMW storm, no strong-scope loads --
// the cheapest coherent poll on this chip). Watchdog latch keeps it hang-proof.
__device__ __forceinline__ void grid_sync_128() {
    __syncthreads();
    if (threadIdx.x == 0) {
        if (__ldcg(&g_abort) == 0u) {
            __threadfence();
            unsigned gen = __ldcg(&g_gen_v);             // own generation BEFORE arriving
            if (atomicAdd(&g_cnt, 1u) == NCTA_LSTM - 1) {
                atomicExch(&g_cnt, 0u);
                __threadfence();
                atomicExch(&g_gen_v, gen + 1);           // release
            } else {
                unsigned spin = 0;
                while (__ldcg(&g_gen_v) == gen) {
                    __nanosleep(32);
                    if (((++spin) & 1023u) == 0u) {
                        if (__ldcg(&g_abort) != 0u) break;
                        if (spin > (1u << 21)) { atomicExch(&g_abort, 1u); break; }
                    }
                }
            }
            __threadfence();
        }
    }
    __syncthreads();
}

// CTA c owns h-columns J = {4c..4c+3}: gate rows g*512 + J for g in {i,f,g,o}.
// Thread (ri = tid&15, kg = tid>>4): row ri = g*4+jloc of the 16 rows, K-slice kg (32 k).
// W slice lives in registers as packed (w,w) f32x2 for all 1024 steps.
// Phase A: 16x512x32 partial products via FFMA2 over batch pairs -> intra-CTA smem partials.
// Gate stage (tid<128): reduce 16 K-groups + xw, activations, h/c update. ONE grid sync/step.
__global__ void __launch_bounds__(256, 1) lstm_kernel(
    const float* __restrict__ xw, const float* __restrict__ w_hh,
    const float* __restrict__ c0)
{
    extern __shared__ char smem_raw[];
    float*    hs   = reinterpret_cast<float*>(smem_raw);            // [512][32] = 64KB
    uint64_t* part = reinterpret_cast<uint64_t*>(smem_raw + 65536); // 16 kg * (16 ri * 18) u64 = 36KB

    const int cta  = blockIdx.x;
    const int tid  = threadIdx.x;
    const int ri   = tid & 15;
    const int kg   = tid >> 4;
    const int warp = tid >> 5;
    const int lane = tid & 31;
    const int c4   = cta * 4;

    // W_hh slice resident in registers (packed pairs) for all steps
    uint64_t wpack[32];
    {
        const int g = ri >> 2, jl = ri & 3;
        const float* wrow = w_hh + (size_t)(g * H_ + c4 + jl) * H_ + (kg << 5);
        #pragma unroll
        for (int q = 0; q < 8; q++) {
            float4 wv = *reinterpret_cast<const float4*>(wrow + q * 4);
            wpack[q * 4 + 0] = pack2(wv.x);
            wpack[q * 4 + 1] = pack2(wv.y);
            wpack[q * 4 + 2] = pack2(wv.z);
            wpack[q * 4 + 3] = pack2(wv.w);
        }
    }

    // gate-stage ownership (threads 0..127): cell (jloc, bb), c in register
    const int jloc = tid >> 5;
    const int bb   = tid & 31;
    float cstate = 0.f;
    if (tid < 128) cstate = c0[bb * H_ + c4 + jloc];

    for (int t = 0; t < T_; t++) {
        const int cur = t & 1;

        // Warp-local h slice load: warp w needs K-slices {2w, 2w+1} = 2048 contiguous
        // floats of transposed h. Bypass L1 (written by other CTAs last step).
        {
            const float4* src = reinterpret_cast<const float4*>(&g_hT[cur][warp * 2048]);
            float4*       dst = reinterpret_cast<float4*>(&hs[warp * 2048]);
            #pragma unroll
            for (int i = 0; i < 16; i++)
                dst[i * 32 + lane] = __ldcg(&src[i * 32 + lane]);
        }

        // Prefetch xw gate biases for (bb, t) — latency hidden under FMA phase
        float xr0 = 0.f, xr1 = 0.f, xr2 = 0.f, xr3 = 0.f;
        if (tid < 128) {
            const float* xp = xw + (size_t)((bb << 10) | t) * G4_ + c4 + jloc;
            xr0 = __ldcg(xp);
            xr1 = __ldcg(xp + H_);
            xr2 = __ldcg(xp + 2 * H_);
            xr3 = __ldcg(xp + 3 * H_);
        }
        __syncwarp();

        // Phase A: 32 k x 32 b per thread via packed FFMA2 (b-pairs)
        uint64_t acc[16];
        #pragma unroll
        for (int q = 0; q < 16; q++) acc[q] = 0ull;
        const float* hsl = hs + (kg << 10);
        #pragma unroll
        for (int k = 0; k < 32; k++) {
            const ulonglong2* hp = reinterpret_cast<const ulonglong2*>(hsl + (k << 5));
            const uint64_t w2 = wpack[k];
            #pragma unroll
            for (int q = 0; q < 8; q++) {
                ulonglong2 hv = hp[q];
                acc[2 * q]     = ffma2(w2, hv.x, acc[2 * q]);
                acc[2 * q + 1] = ffma2(w2, hv.y, acc[2 * q + 1]);
            }
        }
        // store partials (ri-stride padded to 18 u64 = 144B)
        {
            ulonglong2* pp = reinterpret_cast<ulonglong2*>(part + kg * 288 + ri * 18);
            #pragma unroll
            for (int q = 0; q < 8; q++)
                pp[q] = make_ulonglong2(acc[2 * q], acc[2 * q + 1]);
        }
        __syncthreads();

        // Gate stage: reduce K-groups + activations + state update
        if (tid < 128) {
            const float* pf = reinterpret_cast<const float*>(part);
            float s0 = xr0, s1 = xr1, s2 = xr2, s3 = xr3;
            #pragma unroll
            for (int q = 0; q < 16; q++) {
                const float* base = pf + q * 576 + bb;
                s0 += base[(0 * 4 + jloc) * 36];
                s1 += base[(1 * 4 + jloc) * 36];
                s2 += base[(2 * 4 + jloc) * 36];
                s3 += base[(3 * 4 + jloc) * 36];
            }
            float ig = fast_sigmoid(s0);
            float fg = fast_sigmoid(s1);
            float gg = fast_tanh(s2);
            float og = fast_sigmoid(s3);
            cstate   = fg * cstate + ig * gg;
            float hn = og * fast_tanh(cstate);
            g_hT[cur ^ 1][(c4 + jloc) * 32 + bb] = hn;                  // coalesced (b-lanes)
            g_rout[(size_t)((bb << 10) | t) * H_ + c4 + jloc] = hn;     // standard layout
        }
        grid_sync_128();
    }
    if (tid < 128) g_cbuf[bb * H_ + c4 + jloc] = cstate;
}

// ---------------- causal softmax pooling via online cumulative scan ----------------
__global__ void __launch_bounds__(512) attn_scan_kernel() {
    const int a = blockIdx.x >> 5;     // 0 = state attn, 1 = reward attn
    const int b = blockIdx.x & 31;
    const float* e   = &g_e[a * BT_ + b * T_];
    const float* sh  = &g_shared[(size_t)b * T_ * H_];
    float*       ctx = (a == 0) ? &g_ctx0[(size_t)b * T_ * H_]
                                : &g_ctx1[(size_t)b * T_ * H_];
    const int i = threadIdx.x;
    float m = -1e30f, Z = 0.f, s = 0.f;
    for (int t = 0; t < T_; t++) {
        float ev = e[t];
        float x  = sh[(size_t)t * H_ + i];
        float mn = fmaxf(m, ev);
        float corr = __expf(m - mn);
        float w    = __expf(ev - mn);
        Z = Z * corr + w;
        s = s * corr + w * x;
        m = mn;
        ctx[(size_t)t * H_ + i] = __fdividef(s, Z);
    }
}

// ---------------- reward head: dot(ctx_ra, w_rw) + b_rw ----------------
__global__ void __launch_bounds__(256) reward_kernel(
    const float* __restrict__ w_rw, const float* __restrict__ b_rw,
    float* __restrict__ out)
{
    const int warp = threadIdx.x >> 5, lane = threadIdx.x & 31;
    const int token = blockIdx.x * 8 + warp;
    const float* c = &g_ctx1[(size_t)token * H_];
    float p = 0.f;
    #pragma unroll
    for (int i = lane; i < H_; i += 32) p += c[i] * w_rw[i];
    #pragma unroll
    for (int off = 16; off > 0; off >>= 1)
        p += __shfl_down_sync(0xffffffffu, p, off);
    if (lane == 0) out[token] = p + b_rw[0];
}

// ---------------- pack hT, cT ----------------
__global__ void pack_kernel(float* __restrict__ out_h, float* __restrict__ out_c) {
    int i = blockIdx.x * blockDim.x + threadIdx.x;   // i = b*512 + j
    if (i < B_ * H_) {
        int b = i >> 9, j = i & 511;
        out_h[i] = g_hT[0][j * 32 + b];   // T even: final h lives in buffer 0
        out_c[i] = g_cbuf[i];
    }
}

// ---------------- launch ----------------
extern "C" void kernel_launch(void* const* d_in, const int* in_sizes, int n_in,
                              void* d_out, int out_size) {
    const float* x     = (const float*)d_in[0];
    // d_in[1] = x_lengths (int64), all == T -> pack/pad identity, ignored
    const float* h0    = (const float*)d_in[2];
    const float* c0    = (const float*)d_in[3];
    const float* w_ih  = (const float*)d_in[4];
    const float* w_hh  = (const float*)d_in[5];
    const float* b_ih  = (const float*)d_in[6];
    const float* b_hh  = (const float*)d_in[7];
    const float* w_sh  = (const float*)d_in[8];
    const float* b_sh  = (const float*)d_in[9];
    const float* w_sa  = (const float*)d_in[10];
    const float* b_sa  = (const float*)d_in[11];
    const float* v_sa  = (const float*)d_in[12];
    const float* bv_sa = (const float*)d_in[13];
    const float* w_ra  = (const float*)d_in[14];
    const float* b_ra  = (const float*)d_in[15];
    const float* v_ra  = (const float*)d_in[16];
    const float* bv_ra = (const float*)d_in[17];
    const float* w_st  = (const float*)d_in[18];
    const float* b_st  = (const float*)d_in[19];
    const float* w_rw  = (const float*)d_in[20];
    const float* b_rw  = (const float*)d_in[21];

    float* out        = (float*)d_out;
    float* out_state  = out;                       // [B,T,F]  = 2064384
    float* out_reward = out + 2064384;             // [B,T,1]  = 32768
    float* out_hT     = out + 2097152;             // [B,H]    = 16384
    float* out_cT     = out + 2113536;             // [B,H]    = 16384

    float *p_xw, *p_rout, *p_shared, *p_ctx0, *p_ctx1, *p_e;
    cudaGetSymbolAddress((void**)&p_xw,     g_xw);
    cudaGetSymbolAddress((void**)&p_rout,   g_rout);
    cudaGetSymbolAddress((void**)&p_shared, g_shared);
    cudaGetSymbolAddress((void**)&p_ctx0,   g_ctx0);
    cudaGetSymbolAddress((void**)&p_ctx1,   g_ctx1);
    cudaGetSymbolAddress((void**)&p_e,      g_e);

    const int LSTM_SMEM = 65536 + 36864;   // hs (64KB) + partials (36KB)
    cudaFuncSetAttribute(lstm_kernel, cudaFuncAttributeMaxDynamicSharedMemorySize, LSTM_SMEM);

    // launch index:                                                      (ncu -s 5 -c 1)
    // 0) state init (transposed h buffer) + watchdog reset
    init_state_kernel<<<64, 256>>>(h0);
    // 1) input projection: xw = x @ w_ih^T + b_ih + b_hh    [BT,2048], K=64
    gemm_bias_kernel<<<dim3(G4_ / 64, BT_ / 64), 256>>>(x, w_ih, b_ih, b_hh, p_xw, BT_, G4_, IN_);
    // 2,3,4) spacers so the LSTM sits at launch index 5 for ncu capture
    spacer_kernel<<<1, 32>>>();
    spacer_kernel<<<1, 32>>>();
    spacer_kernel<<<1, 32>>>();
    // 5) persistent LSTM over T=1024 steps   <-- profiled launch
    lstm_kernel<<<NCTA_LSTM, 256, LSTM_SMEM>>>(p_xw, w_hh, c0);
    // 6) shared layer: [BT,512] = rout @ w_sh^T + b_sh
    gemm_bias_kernel<<<dim3(H_ / 64, BT_ / 64), 256>>>(p_rout, w_sh, b_sh, nullptr, p_shared, BT_, H_, H_);
    // 7) state-attention scores
    gemm_bias_kernel<<<dim3(H_ / 64, BT_ / 64), 256>>>(p_shared, w_sa, b_sa, nullptr, p_ctx0, BT_, H_, H_);
    attn_e_kernel<<<BT_, 128>>>(p_ctx0, v_sa, bv_sa, p_e);
    // 8) reward-attention scores
    gemm_bias_kernel<<<dim3(H_ / 64, BT_ / 64), 256>>>(p_shared, w_ra, b_ra, nullptr, p_ctx1, BT_, H_, H_);
    attn_e_kernel<<<BT_, 128>>>(p_ctx1, v_ra, bv_ra, p_e + BT_);
    // 9) causal softmax pooling (both attentions), overwrites ctx buffers
    attn_scan_kernel<<<64, 512>>>();
    // 10) state head -> d_out directly
    gemm_bias_kernel<<<dim3(1, BT_ / 64), 256>>>(p_ctx0, w_st, b_st, nullptr, out_state, BT_, F_, H_);
    // 11) reward head
    reward_kernel<<<4096, 256>>>(w_rw, b_rw, out_reward);
    // 12) final states
    pack_kernel<<<64, 256>>>(out_hT, out_cT);
}